// round 1
// baseline (speedup 1.0000x reference)
#include <cuda_runtime.h>
#include <math.h>

#define BB 64
#define NN 2048
#define MM 2048
#define CC 64
#define HH 128
#define NNZE 32768
#define H3 384

// -------- scratch (static device allocations; no runtime malloc) --------
__device__ int   g_rowcnt[BB*MM];
__device__ int   g_rowoff[BB*MM];
__device__ int   g_rowcur[BB*MM];
__device__ int   g_cluscnt[BB*CC];
__device__ int   g_clusoff[BB*CC];
__device__ int   g_cluscur[BB*CC];
__device__ int   g_rowperm[BB*MM];
__device__ int2  g_csr[BB*NNZE];
__device__ float g_pool_s[BB*CC*HH];
__device__ float g_pool_mx[BB*CC*HH];
__device__ float g_ccnt[BB*CC];
__device__ float g_xdec[BB*CC*H3];
__device__ float g_Q[BB*CC*HH];
__device__ float g_K[BB*CC*HH];
__device__ float g_V[BB*CC*HH];

// -------- K0: zero counters --------
__global__ void k_init() {
    int i0 = blockIdx.x * blockDim.x + threadIdx.x;
    int stride = gridDim.x * blockDim.x;
    for (int j = i0; j < BB*MM; j += stride) g_rowcnt[j] = 0;
    for (int j = i0; j < BB*CC; j += stride) g_cluscnt[j] = 0;
}

// -------- K1: histogram rows (per graph) and clusters (per graph) --------
__global__ void k_count(const int* __restrict__ rows, const int* __restrict__ idx) {
    int i0 = blockIdx.x * blockDim.x + threadIdx.x;
    int stride = gridDim.x * blockDim.x;
    for (int i = i0; i < BB*NNZE; i += stride) {
        int g = i >> 15;                       // NNZ = 2^15
        atomicAdd(&g_rowcnt[(g << 11) + rows[i]], 1);
    }
    for (int i = i0; i < BB*MM; i += stride) {
        int g = i >> 11;                       // M = 2^11
        atomicAdd(&g_cluscnt[(g << 6) + idx[i]], 1);
    }
}

// -------- K2: per-graph exclusive scans (rows: 2048, clusters: 64) --------
__global__ void k_scan() {
    __shared__ int ss[1024];
    int g = blockIdx.x, tid = threadIdx.x;
    int base = g * MM;
    int a = g_rowcnt[base + 2*tid];
    int b = g_rowcnt[base + 2*tid + 1];
    int t = a + b;
    ss[tid] = t;
    __syncthreads();
    for (int off = 1; off < 1024; off <<= 1) {
        int v = (tid >= off) ? ss[tid - off] : 0;
        __syncthreads();
        ss[tid] += v;
        __syncthreads();
    }
    int excl = ss[tid] - t;
    g_rowoff[base + 2*tid]     = excl;       g_rowcur[base + 2*tid]     = excl;
    g_rowoff[base + 2*tid + 1] = excl + a;   g_rowcur[base + 2*tid + 1] = excl + a;
    if (tid == 0) {
        int acc = 0;
        for (int c = 0; c < CC; c++) {
            int cc = g_cluscnt[g*CC + c];
            g_clusoff[g*CC + c] = acc;
            g_cluscur[g*CC + c] = acc;
            acc += cc;
        }
    }
}

// -------- K3: scatter edges into CSR; scatter rows into cluster bins --------
__global__ void k_scatter(const int* __restrict__ rows, const int* __restrict__ cols,
                          const float* __restrict__ vals, const int* __restrict__ idx) {
    int i0 = blockIdx.x * blockDim.x + threadIdx.x;
    int stride = gridDim.x * blockDim.x;
    for (int i = i0; i < BB*NNZE; i += stride) {
        int g = i >> 15;
        int r = rows[i];
        int p = atomicAdd(&g_rowcur[(g << 11) + r], 1);
        g_csr[(g << 15) + p] = make_int2(cols[i], __float_as_int(vals[i]));
    }
    for (int i = i0; i < BB*MM; i += stride) {
        int g = i >> 11;
        int c = idx[i];
        int p = atomicAdd(&g_cluscur[(g << 6) + c], 1);
        g_rowperm[(g << 11) + p] = i & (MM - 1);
    }
}

// -------- K4: fused SpMM + cluster pooling. Warp = (graph, cluster). --------
// No atomics: warp owns its cluster's rows, keeps running sum/max in regs.
__global__ void __launch_bounds__(256) k_spmm_pool(const float4* __restrict__ x4) {
    int wg = blockIdx.x * 8 + (threadIdx.x >> 5);   // 0..4095
    int lane = threadIdx.x & 31;
    int g = wg >> 6;
    int c = wg & 63;
    int coff = g_clusoff[(g << 6) + c];
    int ccnt = g_cluscnt[(g << 6) + c];
    const float4* xg = x4 + (size_t)(g << 11) * 32;     // graph's x block, float4 view
    const int2*  csr  = g_csr     + ((size_t)g << 15);
    const int*   perm = g_rowperm + (g << 11);
    const int*   roff = g_rowoff  + (g << 11);
    const int*   rcnt = g_rowcnt  + (g << 11);

    float4 s  = make_float4(0.f, 0.f, 0.f, 0.f);
    float4 mx = make_float4(-INFINITY, -INFINITY, -INFINITY, -INFINITY);

    for (int i = 0; i < ccnt; i++) {
        int row = perm[coff + i];
        int eo = roff[row];
        int el = rcnt[row];
        float4 acc = make_float4(0.f, 0.f, 0.f, 0.f);
        #pragma unroll 4
        for (int e = 0; e < el; e++) {
            int2 p = __ldg(&csr[eo + e]);       // uniform across warp (broadcast)
            float v = __int_as_float(p.y);
            float4 xv = __ldg(&xg[p.x * 32 + lane]);
            acc.x += v * xv.x; acc.y += v * xv.y;
            acc.z += v * xv.z; acc.w += v * xv.w;
        }
        s.x += acc.x; s.y += acc.y; s.z += acc.z; s.w += acc.w;
        mx.x = fmaxf(mx.x, acc.x); mx.y = fmaxf(mx.y, acc.y);
        mx.z = fmaxf(mx.z, acc.z); mx.w = fmaxf(mx.w, acc.w);
    }
    int o = ((g << 6) + c) * 32 + lane;
    ((float4*)g_pool_s)[o]  = s;
    ((float4*)g_pool_mx)[o] = mx;
    if (lane == 0) g_ccnt[(g << 6) + c] = (float)ccnt;
}

// -------- K5: assemble x_dec = [mean | max | sum] --------
__global__ void k_xdec() {
    int i = blockIdx.x * 256 + threadIdx.x;
    if (i >= BB*CC*HH) return;
    int gc = i >> 7;
    int h = i & 127;
    float s = g_pool_s[i];
    float m = g_pool_mx[i];
    float cnt = g_ccnt[gc];
    float mean = s / fmaxf(cnt, 1.0f);
    float* xd = g_xdec + gc * H3;
    xd[h]        = mean;
    xd[HH + h]   = m;
    xd[2*HH + h] = s;
}

// -------- K6: Q/K/V = x_dec @ W  (grid: 64 graphs x 3 matrices) --------
// smem: xsT transposed [384][68 pad], W tile [64][128]. 4x8 microtile / thread.
__global__ void __launch_bounds__(256) k_gemm(const float* __restrict__ Wq,
                                              const float* __restrict__ Wk,
                                              const float* __restrict__ Wv) {
    extern __shared__ float sm[];
    float* xsT = sm;                 // 384 * 68 floats
    float* ws  = sm + 384 * 68;      // 64 * 128 floats
    int g = blockIdx.x, which = blockIdx.y;
    const float* W = (which == 0) ? Wq : (which == 1) ? Wk : Wv;
    float* out = ((which == 0) ? g_Q : (which == 1) ? g_K : g_V) + g * CC * HH;
    int tid = threadIdx.x;

    const float* xd = g_xdec + g * CC * H3;
    for (int i = tid; i < CC * H3; i += 256) {
        int r = i / H3;
        int k = i - r * H3;
        xsT[k * 68 + r] = xd[i];
    }

    int ty = tid >> 4, tx = tid & 15;
    float acc[4][8];
    #pragma unroll
    for (int i = 0; i < 4; i++)
        #pragma unroll
        for (int j = 0; j < 8; j++) acc[i][j] = 0.f;

    for (int kt = 0; kt < H3; kt += 64) {
        __syncthreads();
        const float4* wsrc = (const float4*)(W + kt * HH);   // contiguous 32KB tile
        float4* wdst = (float4*)ws;
        for (int i = tid; i < 64 * HH / 4; i += 256) wdst[i] = wsrc[i];
        __syncthreads();
        #pragma unroll
        for (int kk = 0; kk < 64; kk++) {
            float4 a  = *(const float4*)&xsT[(kt + kk) * 68 + ty * 4];
            float4 b0 = *(const float4*)&ws[kk * HH + tx * 8];
            float4 b1 = *(const float4*)&ws[kk * HH + tx * 8 + 4];
            float av[4] = {a.x, a.y, a.z, a.w};
            float bv[8] = {b0.x, b0.y, b0.z, b0.w, b1.x, b1.y, b1.z, b1.w};
            #pragma unroll
            for (int i = 0; i < 4; i++)
                #pragma unroll
                for (int j = 0; j < 8; j++) acc[i][j] += av[i] * bv[j];
        }
    }
    #pragma unroll
    for (int i = 0; i < 4; i++) {
        float4 o0 = make_float4(acc[i][0], acc[i][1], acc[i][2], acc[i][3]);
        float4 o1 = make_float4(acc[i][4], acc[i][5], acc[i][6], acc[i][7]);
        *(float4*)&out[(ty*4 + i) * HH + tx*8]     = o0;
        *(float4*)&out[(ty*4 + i) * HH + tx*8 + 4] = o1;
    }
}

// -------- K7: per-graph attention: softmax(Q K^T / sqrt(H)) V --------
__global__ void __launch_bounds__(256) k_attn(float* __restrict__ out) {
    extern __shared__ float sm[];
    float* Qs = sm;                   // 64 * 132 (pad)
    float* Ks = Qs + 64 * 132;
    float* Vs = Ks + 64 * 132;
    float* Ss = Vs + 64 * 132;        // 64 * 68 (pad)
    int g = blockIdx.x, tid = threadIdx.x;
    const float* Qg = g_Q + g * CC * HH;
    const float* Kg = g_K + g * CC * HH;
    const float* Vg = g_V + g * CC * HH;

    for (int i = tid; i < CC * HH; i += 256) {
        int r = i >> 7, h = i & 127;
        Qs[r*132 + h] = Qg[i];
        Ks[r*132 + h] = Kg[i];
        Vs[r*132 + h] = Vg[i];
    }
    __syncthreads();

    int r = tid & 63, grp = tid >> 6;   // warp shares grp -> K/V loads broadcast
    // S = Q K^T * scale : thread computes S[r][grp*16 .. +16]
    {
        float sacc[16];
        #pragma unroll
        for (int cc = 0; cc < 16; cc++) sacc[cc] = 0.f;
        const float4* q4 = (const float4*)Qs + r * 33;
        const float4* k4 = (const float4*)Ks;
        #pragma unroll 2
        for (int h4 = 0; h4 < 32; h4++) {
            float4 q = q4[h4];
            #pragma unroll
            for (int cc = 0; cc < 16; cc++) {
                float4 k = k4[(grp*16 + cc) * 33 + h4];
                sacc[cc] += q.x*k.x + q.y*k.y + q.z*k.z + q.w*k.w;
            }
        }
        const float scale = 0.08838834764831845f;   // 1/sqrt(128)
        #pragma unroll
        for (int cc = 0; cc < 16; cc++) Ss[r*68 + grp*16 + cc] = sacc[cc] * scale;
    }
    __syncthreads();
    // softmax rows (one thread per row)
    if (tid < 64) {
        float m = -INFINITY;
        for (int c = 0; c < CC; c++) m = fmaxf(m, Ss[tid*68 + c]);
        float sum = 0.f;
        for (int c = 0; c < CC; c++) {
            float e = __expf(Ss[tid*68 + c] - m);
            Ss[tid*68 + c] = e;
            sum += e;
        }
        float inv = 1.f / sum;
        for (int c = 0; c < CC; c++) Ss[tid*68 + c] *= inv;
    }
    __syncthreads();
    // O = P V : thread computes O[r][grp*32 .. +32]
    {
        float4 acc[8];
        #pragma unroll
        for (int j = 0; j < 8; j++) acc[j] = make_float4(0.f, 0.f, 0.f, 0.f);
        const float4* v4 = (const float4*)Vs;
        for (int c = 0; c < CC; c++) {
            float p = Ss[r*68 + c];
            const float4* vrow = v4 + c * 33 + grp * 8;
            #pragma unroll
            for (int j = 0; j < 8; j++) {
                float4 v = vrow[j];
                acc[j].x += p * v.x; acc[j].y += p * v.y;
                acc[j].z += p * v.z; acc[j].w += p * v.w;
            }
        }
        float4* o4 = (float4*)out + g * 2048 + r * 32 + grp * 8;
        #pragma unroll
        for (int j = 0; j < 8; j++) o4[j] = acc[j];
    }
}

extern "C" void kernel_launch(void* const* d_in, const int* in_sizes, int n_in,
                              void* d_out, int out_size) {
    const float* x    = (const float*)d_in[0];
    // d_in[1] = batch (unused: nodes sorted, equal graph size)
    // d_in[2] = batch_size (compile-time constant BB)
    const int*   rows = (const int*)d_in[3];
    const int*   cols = (const int*)d_in[4];
    const float* vals = (const float*)d_in[5];
    const int*   idx  = (const int*)d_in[6];
    const float* Wq   = (const float*)d_in[7];
    const float* Wk   = (const float*)d_in[8];
    const float* Wv   = (const float*)d_in[9];
    float* out = (float*)d_out;

    static const int GEMM_SMEM = (384*68 + 64*128) * 4;       // 137216 B
    static const int ATTN_SMEM = (3*64*132 + 64*68) * 4;      // 118784 B
    cudaFuncSetAttribute(k_gemm, cudaFuncAttributeMaxDynamicSharedMemorySize, GEMM_SMEM);
    cudaFuncSetAttribute(k_attn, cudaFuncAttributeMaxDynamicSharedMemorySize, ATTN_SMEM);

    k_init<<<256, 256>>>();
    k_count<<<1024, 256>>>(rows, idx);
    k_scan<<<64, 1024>>>();
    k_scatter<<<1024, 256>>>(rows, cols, vals, idx);
    k_spmm_pool<<<512, 256>>>((const float4*)x);
    k_xdec<<<(BB*CC*HH + 255)/256, 256>>>();
    k_gemm<<<dim3(BB, 3), 256, GEMM_SMEM>>>(Wq, Wk, Wv);
    k_attn<<<BB, 256, ATTN_SMEM>>>(out);
}

// round 2
// speedup vs baseline: 1.1539x; 1.1539x over previous
#include <cuda_runtime.h>
#include <math.h>

#define BB 64
#define MM 2048
#define CC 64
#define HH 128
#define NNZE 32768
#define H3 384

// -------- scratch (static device arrays; no runtime malloc) --------
__device__ int   g_rowcnt[BB*MM];
__device__ int   g_rowoff[BB*MM];
__device__ int   g_cluscnt[BB*CC];
__device__ int   g_clusoff[BB*CC];
__device__ int   g_rowperm[BB*MM];
__device__ int2  g_csr[BB*NNZE];
__device__ float g_xdec[BB*CC*H3];
__device__ float g_Q[BB*CC*HH];
__device__ float g_K[BB*CC*HH];
__device__ float g_V[BB*CC*HH];

// ============ K1: fused per-graph histogram + scan + scatter ============
// One CTA per graph. Row CSR (2048 bins) and cluster bins (64) built with
// smem atomics; replaces 4 gmem-atomic kernels.
__global__ void __launch_bounds__(1024) k_prep(const int* __restrict__ rows,
                                               const int* __restrict__ cols,
                                               const float* __restrict__ vals,
                                               const int* __restrict__ idx) {
    __shared__ int hist[MM];
    __shared__ int cur[MM];
    __shared__ int ss[1024];
    __shared__ int chist[CC];
    __shared__ int ccur[CC];
    int g = blockIdx.x, tid = threadIdx.x;
    hist[tid] = 0; hist[tid + 1024] = 0;
    if (tid < CC) chist[tid] = 0;
    __syncthreads();

    const int* r  = rows + g * NNZE;
    const int* ix = idx  + g * MM;
    for (int i = tid; i < NNZE; i += 1024) atomicAdd(&hist[r[i]], 1);
    int i0 = ix[tid], i1 = ix[tid + 1024];
    atomicAdd(&chist[i0], 1);
    atomicAdd(&chist[i1], 1);
    __syncthreads();

    // exclusive scan of 2048 row counts (2 per thread, Hillis-Steele on 1024)
    int a = hist[2*tid], b = hist[2*tid + 1];
    int t = a + b;
    ss[tid] = t;
    __syncthreads();
    for (int off = 1; off < 1024; off <<= 1) {
        int v = (tid >= off) ? ss[tid - off] : 0;
        __syncthreads();
        ss[tid] += v;
        __syncthreads();
    }
    int excl = ss[tid] - t;
    int base = g * MM;
    g_rowoff[base + 2*tid]     = excl;      g_rowcnt[base + 2*tid]     = a;
    g_rowoff[base + 2*tid + 1] = excl + a;  g_rowcnt[base + 2*tid + 1] = b;
    cur[2*tid] = excl;  cur[2*tid + 1] = excl + a;
    if (tid == 0) {
        int acc = 0;
        for (int c = 0; c < CC; c++) {
            int cc = chist[c];
            g_clusoff[g*CC + c] = acc;
            g_cluscnt[g*CC + c] = cc;
            ccur[c] = acc;
            acc += cc;
        }
    }
    __syncthreads();

    // scatter edges into row-CSR
    const int*   c = cols + g * NNZE;
    const float* v = vals + g * NNZE;
    for (int i = tid; i < NNZE; i += 1024) {
        int rr = r[i];
        int p = atomicAdd(&cur[rr], 1);
        g_csr[g*NNZE + p] = make_int2(c[i], __float_as_int(v[i]));
    }
    // scatter row ids into cluster bins
    {
        int p0 = atomicAdd(&ccur[i0], 1);
        g_rowperm[base + p0] = tid;
        int p1 = atomicAdd(&ccur[i1], 1);
        g_rowperm[base + p1] = tid + 1024;
    }
}

// ============ K2: SpMM + pooling + x_dec assembly, H sliced in quarters ====
// CTA = (graph, h-quarter). Lane covers one float of the 32-float slice, so
// each edge's x gather is ONE 128B line from a 256KB per-graph slice that
// stays mostly L1-resident. Warp owns 2 clusters -> pooling in registers,
// no atomics. Epilogue writes [mean|max|sum] directly into g_xdec.
__global__ void __launch_bounds__(1024) k_spmm(const float* __restrict__ x) {
    int g = blockIdx.x >> 2, q = blockIdx.x & 3;
    int wid = threadIdx.x >> 5, lane = threadIdx.x & 31;
    const float* xq  = x + (size_t)g * MM * HH + q * 32 + lane;
    const int2*  csr = g_csr + (size_t)g * NNZE;
    const int*   perm = g_rowperm + g * MM;
    const int*   roff = g_rowoff  + g * MM;
    const int*   rcnt = g_rowcnt  + g * MM;

    #pragma unroll
    for (int half = 0; half < 2; half++) {
        int c = wid + half * 32;
        int coff = g_clusoff[g*CC + c];
        int cn   = g_cluscnt[g*CC + c];
        float s = 0.f, mx = -INFINITY;
        for (int i = 0; i < cn; i++) {
            int row = perm[coff + i];
            int eo = roff[row], el = rcnt[row];
            float acc = 0.f;
            #pragma unroll 4
            for (int e = 0; e < el; e++) {
                int2 p = __ldg(&csr[eo + e]);          // warp-uniform broadcast
                acc += __int_as_float(p.y) * __ldg(xq + p.x * HH);
            }
            s += acc;
            mx = fmaxf(mx, acc);
        }
        float cntf = fmaxf((float)cn, 1.f);
        float* xd = g_xdec + (g*CC + c) * H3 + q * 32 + lane;
        xd[0]    = s / cntf;   // mean
        xd[HH]   = mx;         // max
        xd[2*HH] = s;          // sum
    }
}

// ============ K3: Q/K/V = x_dec @ W with packed f32x2 FMA ============
__device__ __forceinline__ void ffma2(unsigned long long& d,
                                      unsigned long long a,
                                      unsigned long long b) {
    asm("fma.rn.f32x2 %0, %1, %2, %0;" : "+l"(d) : "l"(a), "l"(b));
}
__device__ __forceinline__ unsigned long long pack2(float v) {
    unsigned long long r;
    asm("mov.b64 %0, {%1, %1};" : "=l"(r) : "f"(v));
    return r;
}

#define XS_LD 68
__global__ void __launch_bounds__(256) k_gemm(const float* __restrict__ Wq,
                                              const float* __restrict__ Wk,
                                              const float* __restrict__ Wv) {
    extern __shared__ float sm[];
    float* xs = sm;                // [64 k][68 pad] transposed A tile
    float* ws = sm + 64 * XS_LD;   // [64 k][128 h] W tile
    int g = blockIdx.x, which = blockIdx.y;
    const float* W = (which == 0) ? Wq : (which == 1) ? Wk : Wv;
    float* out = ((which == 0) ? g_Q : (which == 1) ? g_K : g_V) + g * CC * HH;
    const float* xd = g_xdec + g * CC * H3;
    int tid = threadIdx.x;
    int ty = tid >> 4, tx = tid & 15;

    unsigned long long acc[4][4];
    #pragma unroll
    for (int i = 0; i < 4; i++)
        #pragma unroll
        for (int j = 0; j < 4; j++) acc[i][j] = 0ull;

    for (int kt = 0; kt < H3; kt += 64) {
        __syncthreads();
        for (int i = tid; i < 64 * 64; i += 256) {
            int rr = i >> 6, kk = i & 63;
            xs[kk * XS_LD + rr] = xd[rr * H3 + kt + kk];
        }
        const float4* wsrc = (const float4*)(W + kt * HH);
        for (int i = tid; i < 64 * HH / 4; i += 256) ((float4*)ws)[i] = wsrc[i];
        __syncthreads();
        #pragma unroll 4
        for (int kk = 0; kk < 64; kk++) {
            float4 av = *(const float4*)&xs[kk * XS_LD + ty * 4];
            const unsigned long long* bp =
                (const unsigned long long*)&ws[kk * HH + tx * 8];
            unsigned long long pa0 = pack2(av.x), pa1 = pack2(av.y);
            unsigned long long pa2 = pack2(av.z), pa3 = pack2(av.w);
            #pragma unroll
            for (int j = 0; j < 4; j++) {
                unsigned long long b = bp[j];
                ffma2(acc[0][j], pa0, b);
                ffma2(acc[1][j], pa1, b);
                ffma2(acc[2][j], pa2, b);
                ffma2(acc[3][j], pa3, b);
            }
        }
    }
    #pragma unroll
    for (int i = 0; i < 4; i++) {
        unsigned long long* o =
            (unsigned long long*)&out[(ty*4 + i) * HH + tx * 8];
        #pragma unroll
        for (int j = 0; j < 4; j++) o[j] = acc[i][j];
    }
}

// ============ K4: per-graph attention softmax(QK^T/sqrt(H)) V ============
__global__ void __launch_bounds__(256) k_attn(float* __restrict__ out) {
    extern __shared__ float sm[];
    float* Qs = sm;                   // 64 * 132 (pad)
    float* Ks = Qs + 64 * 132;
    float* Vs = Ks + 64 * 132;
    float* Ss = Vs + 64 * 132;        // 64 * 68 (pad)
    int g = blockIdx.x, tid = threadIdx.x;
    const float* Qg = g_Q + g * CC * HH;
    const float* Kg = g_K + g * CC * HH;
    const float* Vg = g_V + g * CC * HH;

    for (int i = tid; i < CC * HH; i += 256) {
        int r = i >> 7, h = i & 127;
        Qs[r*132 + h] = Qg[i];
        Ks[r*132 + h] = Kg[i];
        Vs[r*132 + h] = Vg[i];
    }
    __syncthreads();

    int r = tid & 63, grp = tid >> 6;
    {
        float sacc[16];
        #pragma unroll
        for (int cc = 0; cc < 16; cc++) sacc[cc] = 0.f;
        const float4* q4 = (const float4*)Qs + r * 33;
        const float4* k4 = (const float4*)Ks;
        #pragma unroll 2
        for (int h4 = 0; h4 < 32; h4++) {
            float4 q = q4[h4];
            #pragma unroll
            for (int cc = 0; cc < 16; cc++) {
                float4 k = k4[(grp*16 + cc) * 33 + h4];
                sacc[cc] += q.x*k.x + q.y*k.y + q.z*k.z + q.w*k.w;
            }
        }
        const float scale = 0.08838834764831845f;   // 1/sqrt(128)
        #pragma unroll
        for (int cc = 0; cc < 16; cc++) Ss[r*68 + grp*16 + cc] = sacc[cc] * scale;
    }
    __syncthreads();
    if (tid < 64) {
        float m = -INFINITY;
        for (int c = 0; c < CC; c++) m = fmaxf(m, Ss[tid*68 + c]);
        float sum = 0.f;
        for (int c = 0; c < CC; c++) {
            float e = __expf(Ss[tid*68 + c] - m);
            Ss[tid*68 + c] = e;
            sum += e;
        }
        float inv = 1.f / sum;
        for (int c = 0; c < CC; c++) Ss[tid*68 + c] *= inv;
    }
    __syncthreads();
    {
        float4 acc[8];
        #pragma unroll
        for (int j = 0; j < 8; j++) acc[j] = make_float4(0.f, 0.f, 0.f, 0.f);
        const float4* v4 = (const float4*)Vs;
        for (int c = 0; c < CC; c++) {
            float p = Ss[r*68 + c];
            const float4* vrow = v4 + c * 33 + grp * 8;
            #pragma unroll
            for (int j = 0; j < 8; j++) {
                float4 v = vrow[j];
                acc[j].x += p * v.x; acc[j].y += p * v.y;
                acc[j].z += p * v.z; acc[j].w += p * v.w;
            }
        }
        float4* o4 = (float4*)out + g * 2048 + r * 32 + grp * 8;
        #pragma unroll
        for (int j = 0; j < 8; j++) o4[j] = acc[j];
    }
}

extern "C" void kernel_launch(void* const* d_in, const int* in_sizes, int n_in,
                              void* d_out, int out_size) {
    const float* x    = (const float*)d_in[0];
    const int*   rows = (const int*)d_in[3];
    const int*   cols = (const int*)d_in[4];
    const float* vals = (const float*)d_in[5];
    const int*   idx  = (const int*)d_in[6];
    const float* Wq   = (const float*)d_in[7];
    const float* Wk   = (const float*)d_in[8];
    const float* Wv   = (const float*)d_in[9];
    float* out = (float*)d_out;

    static const int GEMM_SMEM = (64*XS_LD + 64*HH) * 4;   // 50176 B
    static const int ATTN_SMEM = (3*64*132 + 64*68) * 4;   // 118784 B
    cudaFuncSetAttribute(k_gemm, cudaFuncAttributeMaxDynamicSharedMemorySize, GEMM_SMEM);
    cudaFuncSetAttribute(k_attn, cudaFuncAttributeMaxDynamicSharedMemorySize, ATTN_SMEM);

    k_prep<<<BB, 1024>>>(rows, cols, vals, idx);
    k_spmm<<<BB * 4, 1024>>>(x);
    k_gemm<<<dim3(BB, 3), 256, GEMM_SMEM>>>(Wq, Wk, Wv);
    k_attn<<<BB, 256, ATTN_SMEM>>>(out);
}